// round 5
// baseline (speedup 1.0000x reference)
#include <cuda_runtime.h>
#include <math.h>

#define BB 2
#define TT 2048
#define CC 1024
#define HH 16
#define DD 64
#define C3 3072
#define MM (BB*TT)          // 4096
#define YELEMS (BB*TT*CC)   // 4194304

#define BQ 128
#define QPSTR 72

// scratch (static device arrays: allocation-free)
__device__ float g_qkv[MM * C3];   // [B*T, 3C]
__device__ float g_yatt[MM * CC];  // [B*T, C]
__device__ float g_mask[HH * TT];  // [H, rel]

__device__ __forceinline__ unsigned f2tf32(float x) {
    unsigned r;
    asm("cvt.rna.tf32.f32 %0, %1;" : "=r"(r) : "f"(x));
    return r;
}

__device__ __forceinline__ void mma_tf32(float c[4], unsigned a0, unsigned a1,
                                         unsigned a2, unsigned a3,
                                         unsigned b0, unsigned b1) {
    asm volatile(
        "mma.sync.aligned.m16n8k8.row.col.f32.tf32.tf32.f32 "
        "{%0,%1,%2,%3}, {%4,%5,%6,%7}, {%8,%9}, {%0,%1,%2,%3};"
        : "+f"(c[0]), "+f"(c[1]), "+f"(c[2]), "+f"(c[3])
        : "r"(a0), "r"(a1), "r"(a2), "r"(a3), "r"(b0), "r"(b1));
}

// FFMA-only exp2 for z <= 0 (clamped at -80). No MUFU.
__device__ __forceinline__ float fexp2(float z) {
    z = fmaxf(z, -80.0f);
    float r = z + 12582912.0f;                       // round z to nearest int
    int zi = __float_as_int(r) - 0x4B400000;
    float f = z - (r - 12582912.0f);                 // f in [-0.5, 0.5]
    float p = 1.3333558e-3f;
    p = fmaf(p, f, 9.6181291e-3f);
    p = fmaf(p, f, 5.5504109e-2f);
    p = fmaf(p, f, 2.4022651e-1f);
    p = fmaf(p, f, 6.9314718e-1f);
    p = fmaf(p, f, 1.0f);
    return __int_as_float(__float_as_int(p) + (zi << 23));
}

// ---------------------------------------------------------------------------
// Pipelined tf32 tensor-core GEMM with bias: out[M,N] = A[M,K] @ W[K,N] + bias
// Block tile 128x128, K-step 64, double-buffered smem, 256 threads (8 warps),
// warp tile 32x64. Per iter: issue LDG for next tile -> compute current stage
// -> cvt+STS next stage -> one sync. Fragment layouts identical to R3/R4.
// ---------------------------------------------------------------------------
#define AKSTR 72
#define A_STG (128 * AKSTR)   // 9216 floats per A stage
#define B_STG (64 * 128)      // 8192 floats per B stage
#define GEMM_SMEM ((2 * A_STG + 2 * B_STG) * 4)  // 139264 bytes

__global__ __launch_bounds__(256, 1) void mma_gemm_pipe(
    const float* __restrict__ A, const float* __restrict__ W,
    const float* __restrict__ bias, float* __restrict__ out,
    int M, int N, int K)
{
    extern __shared__ float gsm[];
    float* As = gsm;                // 2 stages of 128x72
    float* Bs = gsm + 2 * A_STG;    // 2 stages of 64x128

    const int tid = threadIdx.x;
    const int m0 = blockIdx.y * 128, n0 = blockIdx.x * 128;
    const int lane = tid & 31, w = tid >> 5;
    const int wM = w >> 1, wN = w & 1;          // 4 x 2 warp grid
    const int g = lane >> 2, tig = lane & 3;
    const int fswz = (tig & 1) | ((tig & 2) << 1);

    // gmem loader mapping (K-step 64)
    const int arow = tid >> 1, ac0 = (tid & 1) * 32;   // A: 128 rows x 64 cols
    const int brow = tid >> 2, bc0 = (tid & 3) * 32;   // B: 64 rows x 128 cols
    const int bswz = (brow & 1) | ((brow & 2) << 1);

    const float* ag = &A[(size_t)(m0 + arow) * K + ac0];
    const float* bg = &W[(size_t)brow * N + n0 + bc0];

    float4 ar[8], br[8];

    // prologue: load tile 0
#pragma unroll
    for (int u = 0; u < 8; u++) {
        ar[u] = *(const float4*)&ag[u * 4];
        br[u] = *(const float4*)&bg[u * 4];
    }
    // store tile 0 -> stage 0
    {
        float* as = As;
        float* bs = Bs;
#pragma unroll
        for (int u = 0; u < 8; u++) {
            float av[4] = {ar[u].x, ar[u].y, ar[u].z, ar[u].w};
            float bv[4] = {br[u].x, br[u].y, br[u].z, br[u].w};
#pragma unroll
            for (int c = 0; c < 4; c++) {
                int k = ac0 + u * 4 + c;
                int p8 = k & 7;
                int col = (k & ~7) | (((p8 & 3) << 1) | (p8 >> 2));
                as[arow * AKSTR + col] = __uint_as_float(f2tf32(av[c]));
                int n = bc0 + u * 4 + c;
                int bcol = (n & 64) + (n & 7) * 8 + ((n >> 3) & 7);
                int phys = ((bcol >> 2) ^ bswz) * 4 + (bcol & 3);
                bs[brow * 128 + phys] = __uint_as_float(f2tf32(bv[c]));
            }
        }
    }
    __syncthreads();

    float acc[2][8][4];
#pragma unroll
    for (int i = 0; i < 2; i++)
#pragma unroll
        for (int j = 0; j < 8; j++)
#pragma unroll
            for (int c = 0; c < 4; c++) acc[i][j][c] = 0.0f;

    const int NIT = K >> 6;
    for (int it = 0; it < NIT; it++) {
        // issue next tile's loads early
        if (it + 1 < NIT) {
            const float* ag2 = ag + (it + 1) * 64;
            const float* bg2 = bg + (size_t)(it + 1) * 64 * N;
#pragma unroll
            for (int u = 0; u < 8; u++) {
                ar[u] = *(const float4*)&ag2[u * 4];
                br[u] = *(const float4*)&bg2[u * 4];
            }
        }

        // compute current stage
        const float* as = As + (it & 1) * A_STG;
        const float* bs = Bs + (it & 1) * B_STG;
#pragma unroll
        for (int ka = 0; ka < 8; ka++) {
            unsigned a[2][4];
#pragma unroll
            for (int i = 0; i < 2; i++) {
                int r = wM * 32 + i * 16 + g;
                float2 v0 = *(const float2*)&as[r * AKSTR + ka * 8 + 2 * tig];
                float2 v1 = *(const float2*)&as[(r + 8) * AKSTR + ka * 8 + 2 * tig];
                a[i][0] = __float_as_uint(v0.x);
                a[i][1] = __float_as_uint(v1.x);
                a[i][2] = __float_as_uint(v0.y);
                a[i][3] = __float_as_uint(v1.y);
            }
            unsigned b0[8], b1[8];
            {
                int chunk = 16 * wN + 2 * g;
                int r0 = (ka * 8 + tig) * 128;
                int r1 = (ka * 8 + tig + 4) * 128;
                float4 p0 = *(const float4*)&bs[r0 + ((chunk ^ fswz) << 2)];
                float4 p1 = *(const float4*)&bs[r0 + (((chunk + 1) ^ fswz) << 2)];
                float4 q0 = *(const float4*)&bs[r1 + ((chunk ^ fswz) << 2)];
                float4 q1 = *(const float4*)&bs[r1 + (((chunk + 1) ^ fswz) << 2)];
                b0[0] = __float_as_uint(p0.x); b0[1] = __float_as_uint(p0.y);
                b0[2] = __float_as_uint(p0.z); b0[3] = __float_as_uint(p0.w);
                b0[4] = __float_as_uint(p1.x); b0[5] = __float_as_uint(p1.y);
                b0[6] = __float_as_uint(p1.z); b0[7] = __float_as_uint(p1.w);
                b1[0] = __float_as_uint(q0.x); b1[1] = __float_as_uint(q0.y);
                b1[2] = __float_as_uint(q0.z); b1[3] = __float_as_uint(q0.w);
                b1[4] = __float_as_uint(q1.x); b1[5] = __float_as_uint(q1.y);
                b1[6] = __float_as_uint(q1.z); b1[7] = __float_as_uint(q1.w);
            }
#pragma unroll
            for (int i = 0; i < 2; i++)
#pragma unroll
                for (int j = 0; j < 8; j++)
                    mma_tf32(acc[i][j], a[i][0], a[i][1], a[i][2], a[i][3],
                             b0[j], b1[j]);
        }

        // store next tile into the other stage
        if (it + 1 < NIT) {
            float* asn = As + ((it + 1) & 1) * A_STG;
            float* bsn = Bs + ((it + 1) & 1) * B_STG;
#pragma unroll
            for (int u = 0; u < 8; u++) {
                float av[4] = {ar[u].x, ar[u].y, ar[u].z, ar[u].w};
                float bv[4] = {br[u].x, br[u].y, br[u].z, br[u].w};
#pragma unroll
                for (int c = 0; c < 4; c++) {
                    int k = ac0 + u * 4 + c;
                    int p8 = k & 7;
                    int col = (k & ~7) | (((p8 & 3) << 1) | (p8 >> 2));
                    asn[arow * AKSTR + col] = __uint_as_float(f2tf32(av[c]));
                    int n = bc0 + u * 4 + c;
                    int bcol = (n & 64) + (n & 7) * 8 + ((n >> 3) & 7);
                    int phys = ((bcol >> 2) ^ bswz) * 4 + (bcol & 3);
                    bsn[brow * 128 + phys] = __uint_as_float(f2tf32(bv[c]));
                }
            }
        }
        __syncthreads();
    }

    // epilogue: C frag layout rows (g, g+8), cols (2tig, 2tig+1)
#pragma unroll
    for (int i = 0; i < 2; i++) {
#pragma unroll
        for (int j = 0; j < 8; j++) {
            int row = m0 + wM * 32 + i * 16 + g;
            int col = n0 + wN * 64 + j * 8 + 2 * tig;
            float bx = bias[col], by = bias[col + 1];
            float2 o0 = {acc[i][j][0] + bx, acc[i][j][1] + by};
            float2 o1 = {acc[i][j][2] + bx, acc[i][j][3] + by};
            *(float2*)&out[(size_t)row * N + col] = o0;
            *(float2*)&out[(size_t)(row + 8) * N + col] = o1;
        }
    }
}

// ---------------------------------------------------------------------------
// mask table: g_mask[h][rel] = mpos(rel)*wave(rel)  (rel >= 0)
// ---------------------------------------------------------------------------
__global__ void maskgen(const float* __restrict__ sp, const float* __restrict__ pw,
                        const float* __restrict__ rw, float* __restrict__ mask)
{
    int h = blockIdx.x;
    float span   = 2048.0f / (1.0f + __expf(-sp[h]));
    float period = 2.0f + 2.0f / (1.0f + __expf(-pw[h]));
    float ratio  = -0.25f + 0.5f / (1.0f + __expf(-rw[h]));
    float amp = period * 0.25f, offs = period * ratio;
    for (int rel = threadIdx.x; rel < TT; rel += blockDim.x) {
        float relf = (float)rel;
        float mpos = fminf(fmaxf((32.0f - relf + span) * 0.03125f, 0.0f), 1.0f);
        float wave = 0.5f * (cosf(6.283185307179586f * relf / period) + 1.0f) * amp
                     + 0.5f + offs;
        wave = fminf(fmaxf(wave, 0.0f), 1.0f);
        mask[h * TT + rel] = mpos * wave;
    }
}

// ---------------------------------------------------------------------------
// Tensor-core flash attention (unchanged from R4, known-good).
// ---------------------------------------------------------------------------
__global__ __launch_bounds__(256) void attn_mma(
    const float* __restrict__ qkv, const float* __restrict__ span_p,
    const float* __restrict__ gmask, float* __restrict__ yout)
{
    extern __shared__ float sm[];
    float* QP = sm;                    // 128 x 72 (Q staging, then P)
    float* Ks = sm + BQ * QPSTR;       // 64 x 64 (K^T, d-major, swizzled)
    float* Vs = Ks + 64 * 64;          // 64 x 64 (key-major, swizzled)
    float* MT = Vs + 64 * 64;          // 2048 mask entries

    const int tid = threadIdx.x, lane = tid & 31, w = tid >> 5;
    const int g = lane >> 2, tig = lane & 3;
    const int i0 = ((int)gridDim.x - 1 - (int)blockIdx.x) * BQ;  // big blocks first
    const int h = blockIdx.y, b = blockIdx.z;
    const int R = w * 16;
    const int fswz = (tig & 1) | ((tig & 2) << 1);

    for (int t = tid; t < TT; t += 256) MT[t] = gmask[h * TT + t];

    const float span = 2048.0f / (1.0f + __expf(-span_p[h]));

    // stage Q: scaled by 0.125*log2e, tf32, k-permuted, stride 72
    {
        const float SC = 0.125f * 1.4426950408889634f;
        int row = tid >> 1, cb = (tid & 1) * 32;
        const float* src = &qkv[(size_t)(b * TT + i0 + row) * C3 + h * 64 + cb];
#pragma unroll
        for (int u = 0; u < 8; u++) {
            float4 v = *(const float4*)&src[u * 4];
            float vv[4] = {v.x, v.y, v.z, v.w};
#pragma unroll
            for (int c = 0; c < 4; c++) {
                int k = cb + u * 4 + c;
                int p8 = k & 7;
                int col = (k & ~7) | (((p8 & 3) << 1) | (p8 >> 2));
                QP[row * QPSTR + col] = __uint_as_float(f2tf32(vv[c] * SC));
            }
        }
    }
    __syncthreads();

    // Q fragments (register-resident for all key tiles)
    unsigned qf[8][4];
#pragma unroll
    for (int ks = 0; ks < 8; ks++) {
        float2 v0 = *(const float2*)&QP[(R + g) * QPSTR + 8 * ks + 2 * tig];
        float2 v1 = *(const float2*)&QP[(R + g + 8) * QPSTR + 8 * ks + 2 * tig];
        qf[ks][0] = __float_as_uint(v0.x);
        qf[ks][1] = __float_as_uint(v1.x);
        qf[ks][2] = __float_as_uint(v0.y);
        qf[ks][3] = __float_as_uint(v1.y);
    }

    float O[8][4];
#pragma unroll
    for (int a = 0; a < 8; a++)
#pragma unroll
        for (int c = 0; c < 4; c++) O[a][c] = 0.0f;
    float mr[2] = {-1e30f, -1e30f}, lr[2] = {0.0f, 0.0f};

    int jstart = 0;
    {
        float thr = (float)i0 - span - 96.0f;
        if (thr > 0.0f) jstart = ((int)thr / 64) * 64;
    }

    const int irow[2] = {i0 + R + g, i0 + R + g + 8};

    for (int j0 = jstart; j0 <= i0 + BQ - 64; j0 += 64) {
        __syncthreads();
        // load K^T (transpose) and V tiles, tf32, permuted+swizzled
        {
            int key = tid >> 2, db = (tid & 3) * 16;
            const float* kp = &qkv[(size_t)(b * TT + j0 + key) * C3 + CC + h * 64 + db];
            const float* vp = kp + CC;
            int kswz = (key & 1) | ((key & 2) << 1);
            int pk = ((key & 7) << 3) | (key >> 3);
#pragma unroll
            for (int u = 0; u < 4; u++) {
                float4 kv = *(const float4*)&kp[u * 4];
                float4 vv = *(const float4*)&vp[u * 4];
                float ka[4] = {kv.x, kv.y, kv.z, kv.w};
                float va[4] = {vv.x, vv.y, vv.z, vv.w};
#pragma unroll
                for (int c = 0; c < 4; c++) {
                    int d = db + u * 4 + c;
                    int dswz = (d & 1) | ((d & 2) << 1);
                    int physK = ((((pk >> 2) ^ dswz) << 2) | (pk & 3));
                    Ks[d * 64 + physK] = __uint_as_float(f2tf32(ka[c]));
                    int pd = ((d & 7) << 3) | (d >> 3);
                    int physV = ((((pd >> 2) ^ kswz) << 2) | (pd & 3));
                    Vs[key * 64 + physV] = __uint_as_float(f2tf32(va[c]));
                }
            }
        }
        __syncthreads();

        // S = Q @ K^T (log2-scaled logits)
        float S[8][4];
#pragma unroll
        for (int a = 0; a < 8; a++)
#pragma unroll
            for (int c = 0; c < 4; c++) S[a][c] = 0.0f;
#pragma unroll
        for (int ks = 0; ks < 8; ks++) {
            int r0 = (8 * ks + tig) * 64, r1 = (8 * ks + tig + 4) * 64;
            float4 p0 = *(const float4*)&Ks[r0 + (((2 * g) ^ fswz) << 2)];
            float4 p1 = *(const float4*)&Ks[r0 + (((2 * g + 1) ^ fswz) << 2)];
            float4 q0 = *(const float4*)&Ks[r1 + (((2 * g) ^ fswz) << 2)];
            float4 q1 = *(const float4*)&Ks[r1 + (((2 * g + 1) ^ fswz) << 2)];
            unsigned b0[8], b1[8];
            b0[0] = __float_as_uint(p0.x); b0[1] = __float_as_uint(p0.y);
            b0[2] = __float_as_uint(p0.z); b0[3] = __float_as_uint(p0.w);
            b0[4] = __float_as_uint(p1.x); b0[5] = __float_as_uint(p1.y);
            b0[6] = __float_as_uint(p1.z); b0[7] = __float_as_uint(p1.w);
            b1[0] = __float_as_uint(q0.x); b1[1] = __float_as_uint(q0.y);
            b1[2] = __float_as_uint(q0.z); b1[3] = __float_as_uint(q0.w);
            b1[4] = __float_as_uint(q1.x); b1[5] = __float_as_uint(q1.y);
            b1[6] = __float_as_uint(q1.z); b1[7] = __float_as_uint(q1.w);
#pragma unroll
            for (int a = 0; a < 8; a++)
                mma_tf32(S[a], qf[ks][0], qf[ks][1], qf[ks][2], qf[ks][3],
                         b0[a], b1[a]);
        }

        // online softmax per row-pair + P store (own rows only)
#pragma unroll
        for (int r = 0; r < 2; r++) {
            float tmax = -1e30f;
#pragma unroll
            for (int a = 0; a < 8; a++) {
                tmax = fmaxf(tmax, S[a][2 * r]);
                tmax = fmaxf(tmax, S[a][2 * r + 1]);
            }
            tmax = fmaxf(tmax, __shfl_xor_sync(0xffffffffu, tmax, 1));
            tmax = fmaxf(tmax, __shfl_xor_sync(0xffffffffu, tmax, 2));
            float mnew = fmaxf(mr[r], tmax);
            float corr = fexp2(mr[r] - mnew);
            mr[r] = mnew;
            float rsum = 0.0f;
            int prow = (R + g + 8 * r) * QPSTR;
#pragma unroll
            for (int a = 0; a < 8; a++) {
#pragma unroll
                for (int c = 0; c < 2; c++) {
                    int j = j0 + 8 * a + 2 * tig + c;
                    int rel = irow[r] - j;
                    float p = 0.0f;
                    if (rel >= 0)
                        p = fexp2(S[a][2 * r + c] - mnew) * MT[rel];
                    rsum += p;
                    int p8 = 2 * tig + c;
                    int col = 8 * a + (((p8 & 3) << 1) | (p8 >> 2));
                    QP[prow + col] = __uint_as_float(f2tf32(p));
                }
            }
            rsum += __shfl_xor_sync(0xffffffffu, rsum, 1);
            rsum += __shfl_xor_sync(0xffffffffu, rsum, 2);
            lr[r] = lr[r] * corr + rsum;
#pragma unroll
            for (int a = 0; a < 8; a++) {
                O[a][2 * r] *= corr;
                O[a][2 * r + 1] *= corr;
            }
        }
        __syncwarp();

        // O += P @ V
#pragma unroll
        for (int ks = 0; ks < 8; ks++) {
            float2 v0 = *(const float2*)&QP[(R + g) * QPSTR + 8 * ks + 2 * tig];
            float2 v1 = *(const float2*)&QP[(R + g + 8) * QPSTR + 8 * ks + 2 * tig];
            unsigned a0 = __float_as_uint(v0.x), a1 = __float_as_uint(v1.x);
            unsigned a2 = __float_as_uint(v0.y), a3 = __float_as_uint(v1.y);
            int r0 = (8 * ks + tig) * 64, r1 = (8 * ks + tig + 4) * 64;
            float4 p0 = *(const float4*)&Vs[r0 + (((2 * g) ^ fswz) << 2)];
            float4 p1 = *(const float4*)&Vs[r0 + (((2 * g + 1) ^ fswz) << 2)];
            float4 q0 = *(const float4*)&Vs[r1 + (((2 * g) ^ fswz) << 2)];
            float4 q1 = *(const float4*)&Vs[r1 + (((2 * g + 1) ^ fswz) << 2)];
            unsigned b0[8], b1[8];
            b0[0] = __float_as_uint(p0.x); b0[1] = __float_as_uint(p0.y);
            b0[2] = __float_as_uint(p0.z); b0[3] = __float_as_uint(p0.w);
            b0[4] = __float_as_uint(p1.x); b0[5] = __float_as_uint(p1.y);
            b0[6] = __float_as_uint(p1.z); b0[7] = __float_as_uint(p1.w);
            b1[0] = __float_as_uint(q0.x); b1[1] = __float_as_uint(q0.y);
            b1[2] = __float_as_uint(q0.z); b1[3] = __float_as_uint(q0.w);
            b1[4] = __float_as_uint(q1.x); b1[5] = __float_as_uint(q1.y);
            b1[6] = __float_as_uint(q1.z); b1[7] = __float_as_uint(q1.w);
#pragma unroll
            for (int a = 0; a < 8; a++)
                mma_tf32(O[a], a0, a1, a2, a3, b0[a], b1[a]);
        }
    }

    // epilogue: normalize, write y (head-interleaved)
    float inv0 = 1.0f / lr[0], inv1 = 1.0f / lr[1];
#pragma unroll
    for (int a = 0; a < 8; a++) {
        int d = 8 * a + 2 * tig;
        float2 o0 = {O[a][0] * inv0, O[a][1] * inv0};
        float2 o1 = {O[a][2] * inv1, O[a][3] * inv1};
        *(float2*)&yout[(size_t)(b * TT + irow[0]) * CC + h * 64 + d] = o0;
        *(float2*)&yout[(size_t)(b * TT + irow[1]) * CC + h * 64 + d] = o1;
    }
}

// ---------------------------------------------------------------------------
__global__ void loss_kernel(const float* __restrict__ sp, const float* __restrict__ pw,
                            const float* __restrict__ rw, float* __restrict__ out,
                            int out_size)
{
    if (threadIdx.x == 0 && blockIdx.x == 0 && out_size > YELEMS) {
        float a = 0.0f;
        for (int h = 0; h < HH; h++) {
            float span   = 2048.0f / (1.0f + expf(-sp[h]));
            float period = 2.0f + 2.0f / (1.0f + expf(-pw[h]));
            float ratio  = -0.25f + 0.5f / (1.0f + expf(-rw[h]));
            float lt = 1.0f / period + 2.0f * ratio - 0.25f + 0.5f;
            a += (span + 32.0f) * lt;
        }
        out[YELEMS] = 2e-6f * a / (float)HH;
    }
}

// ---------------------------------------------------------------------------
extern "C" void kernel_launch(void* const* d_in, const int* in_sizes, int n_in,
                              void* d_out, int out_size)
{
    const float* x       = (const float*)d_in[0];
    const float* w_attn  = (const float*)d_in[1];
    const float* b_attn  = (const float*)d_in[2];
    const float* w_proj  = (const float*)d_in[3];
    const float* b_proj  = (const float*)d_in[4];
    const float* span_p  = (const float*)d_in[5];
    const float* per_w   = (const float*)d_in[6];
    const float* rat_w   = (const float*)d_in[7];
    float* out = (float*)d_out;

    float *qkvp = nullptr, *yattp = nullptr, *maskp = nullptr;
    cudaGetSymbolAddress((void**)&qkvp, g_qkv);
    cudaGetSymbolAddress((void**)&yattp, g_yatt);
    cudaGetSymbolAddress((void**)&maskp, g_mask);

    const int ATTN_SMEM = (BQ * QPSTR + 64 * 64 * 2 + TT) * (int)sizeof(float); // 77824
    cudaFuncSetAttribute(attn_mma, cudaFuncAttributeMaxDynamicSharedMemorySize, ATTN_SMEM);
    cudaFuncSetAttribute(mma_gemm_pipe, cudaFuncAttributeMaxDynamicSharedMemorySize, GEMM_SMEM);

    // 0. mask table
    maskgen<<<HH, 256>>>(span_p, per_w, rat_w, maskp);
    // 1. QKV projection (pipelined tf32 tensor cores)
    mma_gemm_pipe<<<dim3(C3 / 128, MM / 128), 256, GEMM_SMEM>>>(x, w_attn, b_attn, qkvp, MM, C3, CC);
    // 2. attention (tf32 tensor cores + table mask + FFMA exp)
    attn_mma<<<dim3(TT / BQ, HH, BB), 256, ATTN_SMEM>>>(qkvp, span_p, maskp, yattp);
    // 3. output projection
    mma_gemm_pipe<<<dim3(CC / 128, MM / 128), 256, GEMM_SMEM>>>(yattp, w_proj, b_proj, out, MM, CC, CC);
    // 4. span loss scalar
    loss_kernel<<<1, 32>>>(span_p, per_w, rat_w, out, out_size);
}